// round 2
// baseline (speedup 1.0000x reference)
#include <cuda_runtime.h>

// ---------------------------------------------------------------------------
// CorrelationModule: BN+ReLU+Conv3x3 -> channel L2 norm -> 9x9 dilated corr
// Round 2: packed fp32x2 FMA (fma.rn.f32x2) to beat the scalar-FFMA issue
// roofline (rt_SMSP=2) -> 2x FP32 throughput, identical numerics.
// ---------------------------------------------------------------------------

#define BB    4
#define GG    4      // feature groups
#define CI    128    // channels in (per group)
#define CO    128    // channels out
#define HH    64
#define WW    128
#define NIMG  16     // GG * BB
#define PATCH 9
#define DILP  2
#define PADC  8      // (PATCH/2)*DILP
#define CCHUNK 4

typedef unsigned long long ull;

// packed fp32x2 fma: acc = a*b + acc (elementwise on both 32-bit halves)
#define FMA2(acc, a, b) \
    asm("fma.rn.f32x2 %0, %1, %2, %0;" : "+l"(acc) : "l"(a), "l"(b))

union F2U { ull u; float2 f; };

// Scratch (device globals are the sanctioned scratch mechanism).
__device__ __align__(128) float g_nf[NIMG * HH * WW * CO];   // normalized feats, NHWC
// weights interleaved for pair-FMA: [cin][dy][co_pair(64)][8] ; slots 0..5 =
// (k0.lo,k0.hi,k1.lo,k1.hi,k2.lo,k2.hi) where lo/hi = couts 2p,2p+1; 6..7 pad.
__device__ __align__(128) float g_wt3[CI * 3 * 64 * 8];
__device__ float g_bn_a[CI];
__device__ float g_bn_b[CI];

// ---------------------------------------------------------------------------
// Prep: BN folding + weight transpose/interleave. grid 768 x 256.
// ---------------------------------------------------------------------------
__global__ void prep_kernel(const float* __restrict__ gamma,
                            const float* __restrict__ beta,
                            const float* __restrict__ mean,
                            const float* __restrict__ var,
                            const float* __restrict__ convw) {
    int idx = blockIdx.x * 256 + threadIdx.x;
    if (blockIdx.x == 0 && threadIdx.x < CI) {
        int c = threadIdx.x;
        float a = gamma[c] * rsqrtf(var[c] + 1e-5f);
        g_bn_a[c] = a;
        g_bn_b[c] = beta[c] - mean[c] * a;
    }
    if (idx < CI * 3 * 64 * 8) {
        int r8   = idx & 7;        // slot within pair-group
        int rest = idx >> 3;       // (cin*3+dy)*64 + p
        int p    = rest & 63;
        int rest2 = rest >> 6;
        int dy   = rest2 % 3;
        int cin  = rest2 / 3;
        int k = r8 >> 1;           // tap 0..3 (3 = pad)
        int r = r8 & 1;            // lo/hi cout of the pair
        float v = 0.f;
        if (k < 3) v = convw[((2 * p + r) * CI + cin) * 9 + dy * 3 + k];
        g_wt3[idx] = v;
    }
}

// ---------------------------------------------------------------------------
// Conv: BN+ReLU on load, 3x3 conv via fp32x2 packed FMA, fused channel-L2
// normalize. One block per (row h, image). 256 threads = 16 wg x 16 cg.
// Thread: 8 w x 8 cout (= 8 w x 4 cout-PAIRS packed).
// ---------------------------------------------------------------------------
__global__ __launch_bounds__(256, 2)
void conv_kernel(const float* __restrict__ x) {
    const int h   = blockIdx.x;      // 0..63
    const int img = blockIdx.y;      // 0..15
    const int g   = img >> 2;
    const int b   = img & 3;

    const int tid = threadIdx.x;
    const int cg  = tid >> 4;        // cout group 0..15
    const int wg  = tid & 15;        // w group 0..15
    const int w0  = wg * 8;
    const int cp0 = cg * 4;          // first cout-pair index

    // xs2: duplicated input values {v,v} per (ci,dy,wp): [4*3][264]
    // wsp: interleaved weights: [4*3][64][8]
    __shared__ __align__(16) float xs2[CCHUNK * 3 * 264];   // 12.4 KB
    __shared__ __align__(16) float wsp[CCHUNK * 3 * 64 * 8]; // 24 KB

    ull acc2[8][4];
#pragma unroll
    for (int i = 0; i < 8; i++)
#pragma unroll
        for (int j = 0; j < 4; j++) acc2[i][j] = 0ull;

    for (int cc = 0; cc < CI; cc += CCHUNK) {
        __syncthreads();
        // ---- input rows h-1..h+1 for 4 cins, BN+ReLU, duplicated store
        for (int i = tid; i < CCHUNK * 3 * 130; i += 256) {
            int ci = i / 390;
            int r  = i - ci * 390;
            int dy = r / 130;
            int wp = r - dy * 130;
            int row = h + dy - 1;
            int w   = wp - 1;
            float v = 0.f;
            if ((unsigned)row < (unsigned)HH && (unsigned)w < (unsigned)WW) {
                int cin = cc + ci;
                float xv = x[(((b * (GG * CI)) + g * CI + cin) * HH + row) * WW + w];
                v = fmaxf(fmaf(xv, g_bn_a[cin], g_bn_b[cin]), 0.f);
            }
            int o = (ci * 3 + dy) * 264 + wp * 2;
            xs2[o] = v;
            xs2[o + 1] = v;
        }
        // ---- weights: contiguous copy of this chunk's interleaved block
        {
            const float4* src = (const float4*)(g_wt3 + cc * (3 * 64 * 8));
            float4* dst = (float4*)wsp;
            for (int i = tid; i < CCHUNK * 3 * 64 * 8 / 4; i += 256)
                dst[i] = src[i];
        }
        __syncthreads();

#pragma unroll
        for (int ci = 0; ci < CCHUNK; ci++) {
#pragma unroll
            for (int dy = 0; dy < 3; dy++) {
                // 10 duplicated x pairs covering wp = w0 .. w0+9
                const ulonglong2* px =
                    (const ulonglong2*)&xs2[(ci * 3 + dy) * 264 + w0 * 2];
                ull xd[10];
                {
                    ulonglong2 q0 = px[0], q1 = px[1], q2 = px[2],
                               q3 = px[3], q4 = px[4];
                    xd[0] = q0.x; xd[1] = q0.y;
                    xd[2] = q1.x; xd[3] = q1.y;
                    xd[4] = q2.x; xd[5] = q2.y;
                    xd[6] = q3.x; xd[7] = q3.y;
                    xd[8] = q4.x; xd[9] = q4.y;
                }
                const ulonglong2* pw =
                    (const ulonglong2*)&wsp[((ci * 3 + dy) * 64 + cp0) * 8];
#pragma unroll
                for (int coj = 0; coj < 4; coj++) {
                    ulonglong2 wq0 = pw[coj * 2];
                    ulonglong2 wq1 = pw[coj * 2 + 1];
                    ull wk0 = wq0.x, wk1 = wq0.y, wk2 = wq1.x;
#pragma unroll
                    for (int wi = 0; wi < 8; wi++) {
                        FMA2(acc2[wi][coj], xd[wi],     wk0);
                        FMA2(acc2[wi][coj], xd[wi + 1], wk1);
                        FMA2(acc2[wi][coj], xd[wi + 2], wk2);
                    }
                }
            }
        }
    }

    // ---- channel L2 norm across the block (each w needs all 128 couts)
    __syncthreads();
    float* red = xs2;  // reuse: [16 cout-groups][128 w] = 2048 floats (fits)
#pragma unroll
    for (int wi = 0; wi < 8; wi++) {
        float s = 0.f;
#pragma unroll
        for (int coj = 0; coj < 4; coj++) {
            F2U t; t.u = acc2[wi][coj];
            s = fmaf(t.f.x, t.f.x, s);
            s = fmaf(t.f.y, t.f.y, s);
        }
        red[cg * WW + w0 + wi] = s;
    }
    __syncthreads();

#pragma unroll
    for (int wi = 0; wi < 8; wi++) {
        float n2 = 0.f;
#pragma unroll
        for (int k = 0; k < 16; k++) n2 += red[k * WW + w0 + wi];
        float inv = rsqrtf(n2);
        float o[8];
#pragma unroll
        for (int coj = 0; coj < 4; coj++) {
            F2U t; t.u = acc2[wi][coj];
            o[2 * coj]     = t.f.x * inv;
            o[2 * coj + 1] = t.f.y * inv;
        }
        float* dst = &g_nf[(((img * HH) + h) * WW + (w0 + wi)) * CO + cg * 8];
        *reinterpret_cast<float4*>(dst)     = make_float4(o[0], o[1], o[2], o[3]);
        *reinterpret_cast<float4*>(dst + 4) = make_float4(o[4], o[5], o[6], o[7]);
    }
}

// ---------------------------------------------------------------------------
// Correlation with fp32x2: out[b, pair*81+py*9+px, h, w] =
//   sum_c nf1[b,h,w,c] * nf2[b, h+2py-8, w+2px-8, c]
// Packing over w pairs: since px offsets are even, f2 pairs stay aligned.
// Block = (h, pair*4+b). 144 threads = 9 py x 16 wg; thread: 8w x 9px.
// ---------------------------------------------------------------------------
#define CK 8

__global__ __launch_bounds__(144)
void corr_kernel(float* __restrict__ out) {
    const int h    = blockIdx.x;          // 0..63
    const int pb   = blockIdx.y;          // 0..11
    const int pair = pb >> 2;
    const int b    = pb & 3;
    const int img1 = pair * 4 + b;
    const int img2 = img1 + 4;

    const int tid = threadIdx.x;          // 0..143
    const int py  = tid / 16;             // 0..8
    const int wg  = tid - py * 16;        // 0..15
    const int w0  = wg * 8;

    __shared__ __align__(16) float f2s[PATCH][CK][148]; // [py][c][col], col=w2+8
    __shared__ __align__(16) float f1s[CK][132];        // [c][w]

    ull acc2[4][PATCH];                   // w-pairs x px, packed fp32x2
#pragma unroll
    for (int i = 0; i < 4; i++)
#pragma unroll
        for (int j = 0; j < PATCH; j++) acc2[i][j] = 0ull;

    for (int cch = 0; cch < CO / CK; cch++) {
        const int c0 = cch * CK;
        __syncthreads();
        // f1: 128 w x 8 c  (float4 over c)
        for (int i = tid; i < WW * CK / 4; i += 144) {
            int w  = i >> 1;
            int c4 = (i & 1) * 4;
            float4 v = *reinterpret_cast<const float4*>(
                &g_nf[(((img1 * HH) + h) * WW + w) * CO + c0 + c4]);
            f1s[c4 + 0][w] = v.x;
            f1s[c4 + 1][w] = v.y;
            f1s[c4 + 2][w] = v.z;
            f1s[c4 + 3][w] = v.w;
        }
        // f2: 9 rows x 144 cols x 8 c
        for (int i = tid; i < PATCH * 144 * CK / 4; i += 144) {
            int py2 = i / 288;
            int r   = i - py2 * 288;
            int col = r >> 1;
            int c4  = (r & 1) * 4;
            int row = h + py2 * 2 - PADC;
            int w2  = col - PADC;
            float4 v = make_float4(0.f, 0.f, 0.f, 0.f);
            if ((unsigned)row < (unsigned)HH && (unsigned)w2 < (unsigned)WW) {
                v = *reinterpret_cast<const float4*>(
                    &g_nf[(((img2 * HH) + row) * WW + w2) * CO + c0 + c4]);
            }
            f2s[py2][c4 + 0][col] = v.x;
            f2s[py2][c4 + 1][col] = v.y;
            f2s[py2][c4 + 2][col] = v.z;
            f2s[py2][c4 + 3][col] = v.w;
        }
        __syncthreads();

#pragma unroll
        for (int c = 0; c < CK; c++) {
            ull f1p[4];
            {
                const ulonglong2* p = (const ulonglong2*)&f1s[c][w0];
                ulonglong2 a0 = p[0], a1 = p[1];
                f1p[0] = a0.x; f1p[1] = a0.y; f1p[2] = a1.x; f1p[3] = a1.y;
            }
            ull f2p[12];
            {
                const ulonglong2* p = (const ulonglong2*)&f2s[py][c][w0];
#pragma unroll
                for (int q = 0; q < 6; q++) {
                    ulonglong2 v = p[q];
                    f2p[2 * q]     = v.x;
                    f2p[2 * q + 1] = v.y;
                }
            }
#pragma unroll
            for (int px = 0; px < PATCH; px++)
#pragma unroll
                for (int wj = 0; wj < 4; wj++)
                    FMA2(acc2[wj][px], f1p[wj], f2p[wj + px]);
        }
    }

    // ---- write out
#pragma unroll
    for (int px = 0; px < PATCH; px++) {
        int ch = pair * (PATCH * PATCH) + py * PATCH + px;
        float o[8];
#pragma unroll
        for (int wj = 0; wj < 4; wj++) {
            F2U t; t.u = acc2[wj][px];
            o[2 * wj]     = t.f.x;
            o[2 * wj + 1] = t.f.y;
        }
        float* dst = &out[(((b * (3 * PATCH * PATCH)) + ch) * HH + h) * WW + w0];
        *reinterpret_cast<float4*>(dst)     = make_float4(o[0], o[1], o[2], o[3]);
        *reinterpret_cast<float4*>(dst + 4) = make_float4(o[4], o[5], o[6], o[7]);
    }
}

// ---------------------------------------------------------------------------
extern "C" void kernel_launch(void* const* d_in, const int* in_sizes, int n_in,
                              void* d_out, int out_size) {
    const float* x     = (const float*)d_in[0];
    const float* gamma = (const float*)d_in[1];
    const float* beta  = (const float*)d_in[2];
    const float* mean  = (const float*)d_in[3];
    const float* var   = (const float*)d_in[4];
    const float* convw = (const float*)d_in[5];
    float* out = (float*)d_out;

    prep_kernel<<<768, 256>>>(gamma, beta, mean, var, convw);
    conv_kernel<<<dim3(HH, NIMG), 256>>>(x);
    corr_kernel<<<dim3(HH, 3 * BB), 144>>>(out);
}

// round 5
// speedup vs baseline: 2.5801x; 2.5801x over previous
#include <cuda_runtime.h>
#include <cuda_bf16.h>
#include <cstdint>

// ---------------------------------------------------------------------------
// CorrelationModule on sm_100 (base target -- NO tcgen05, NO f32x2):
//   BN+ReLU -> conv3x3 as mma.sync bf16 split-precision implicit GEMM
//   -> fused channel L2 norm -> 9x9 dilated correlation (scalar fp32).
// ---------------------------------------------------------------------------

#define BB    4
#define GG    4
#define CI    128
#define CO    128
#define HH    64
#define WW    128
#define NIMG  16
#define PATCH 9
#define PADC  8

typedef unsigned int u32;

// ------------------------------ device scratch -----------------------------
__device__ __align__(128) float          g_nf[NIMG * HH * WW * CO];      // 64 MB
__device__ __align__(128) __nv_bfloat16  g_act_hi[NIMG * HH * WW * CI];  // 32 MB
__device__ __align__(128) __nv_bfloat16  g_act_lo[NIMG * HH * WW * CI];  // 32 MB
// weight tiles: tile = (tap*2 + half)*2 + split, each [cout=128][c=64] bf16
__device__ __align__(128) __nv_bfloat16  g_wb[36 * 128 * 64];
__device__ float g_bn_a[CI];
__device__ float g_bn_b[CI];

// ------------------------------ helpers ------------------------------------
__device__ __forceinline__ u32 smem_u32(const void* p) {
    u32 a;
    asm("{ .reg .u64 t; cvta.to.shared.u64 t, %1; cvt.u32.u64 %0, t; }"
        : "=r"(a) : "l"(p));
    return a;
}

#define LDM4(r, addr) \
    asm volatile("ldmatrix.sync.aligned.m8n8.x4.shared.b16 {%0,%1,%2,%3}, [%4];" \
        : "=r"((r)[0]), "=r"((r)[1]), "=r"((r)[2]), "=r"((r)[3]) : "r"(addr))

#define MMA16816(d, a, b0_, b1_) \
    asm volatile("mma.sync.aligned.m16n8k16.row.col.f32.bf16.bf16.f32 " \
        "{%0,%1,%2,%3}, {%4,%5,%6,%7}, {%8,%9}, {%0,%1,%2,%3};" \
        : "+f"((d)[0]), "+f"((d)[1]), "+f"((d)[2]), "+f"((d)[3]) \
        : "r"((a)[0]), "r"((a)[1]), "r"((a)[2]), "r"((a)[3]), "r"(b0_), "r"(b1_))

#define CP_ASYNC16(dst, src, sz) \
    asm volatile("cp.async.cg.shared.global [%0], [%1], 16, %2;" \
                 :: "r"(dst), "l"(src), "r"(sz) : "memory")
#define CP_COMMIT() asm volatile("cp.async.commit_group;" ::: "memory")
#define CP_WAIT1()  asm volatile("cp.async.wait_group 1;" ::: "memory")
#define CP_WAIT0()  asm volatile("cp.async.wait_group 0;" ::: "memory")

// ---------------------------------------------------------------------------
// prep_bn: fold BN into per-channel a,b
// ---------------------------------------------------------------------------
__global__ void prep_bn_kernel(const float* __restrict__ gamma,
                               const float* __restrict__ beta,
                               const float* __restrict__ mean,
                               const float* __restrict__ var) {
    int c = threadIdx.x;
    if (c < CI) {
        float a = gamma[c] * rsqrtf(var[c] + 1e-5f);
        g_bn_a[c] = a;
        g_bn_b[c] = beta[c] - mean[c] * a;
    }
}

// ---------------------------------------------------------------------------
// prep_w: split weights into bf16 hi/lo tiles [cout][64c] per (tap, half).
// ---------------------------------------------------------------------------
__global__ void prep_w_kernel(const float* __restrict__ convw) {
    int im   = blockIdx.x;              // 0..35
    int sp   = im & 1;                  // 0=hi 1=lo
    int half = (im >> 1) & 1;
    int tap  = im >> 2;                 // 0..8
    int dy = tap / 3, dx = tap % 3;
    __nv_bfloat16* base = g_wb + (size_t)im * 8192;
    for (int t = threadIdx.x; t < 128 * 64; t += 256) {
        int cout = t >> 6;
        int cl   = t & 63;
        int cin  = half * 64 + cl;
        float wv = convw[(cout * CI + cin) * 9 + dy * 3 + dx];
        __nv_bfloat16 hi = __float2bfloat16(wv);
        base[t] = (sp == 0) ? hi : __float2bfloat16(wv - __bfloat162float(hi));
    }
}

// ---------------------------------------------------------------------------
// act_split: BN+ReLU, fp32 -> (hi,lo) bf16, NCHW -> NHWC transpose.
// ---------------------------------------------------------------------------
__global__ __launch_bounds__(256)
void act_split_kernel(const float* __restrict__ x) {
    const int img = blockIdx.x, h = blockIdx.y;
    const int g = img >> 2, b = img & 3;
    __shared__ float s[64 * 133];
    const int tid = threadIdx.x;
    const int c2 = tid >> 7;
    const int wl = tid & 127;

    for (int pass = 0; pass < 2; pass++) {
        __syncthreads();
        for (int co = 0; co < 64; co += 2) {
            int cl  = co + c2;
            int cin = pass * 64 + cl;
            float xv = x[(((size_t)b * 512 + g * 128 + cin) * HH + h) * WW + wl];
            s[cl * 133 + wl] = fmaxf(fmaf(xv, g_bn_a[cin], g_bn_b[cin]), 0.f);
        }
        __syncthreads();
        for (int t = tid; t < 2048; t += 256) {
            int w  = t >> 4;
            int cc = t & 15;
            float v0 = s[(cc * 4 + 0) * 133 + w];
            float v1 = s[(cc * 4 + 1) * 133 + w];
            float v2 = s[(cc * 4 + 2) * 133 + w];
            float v3 = s[(cc * 4 + 3) * 133 + w];
            __nv_bfloat16 h0 = __float2bfloat16(v0), h1 = __float2bfloat16(v1);
            __nv_bfloat16 h2 = __float2bfloat16(v2), h3 = __float2bfloat16(v3);
            __nv_bfloat16 l0 = __float2bfloat16(v0 - __bfloat162float(h0));
            __nv_bfloat16 l1 = __float2bfloat16(v1 - __bfloat162float(h1));
            __nv_bfloat16 l2 = __float2bfloat16(v2 - __bfloat162float(h2));
            __nv_bfloat16 l3 = __float2bfloat16(v3 - __bfloat162float(h3));
            uint2 hv, lv;
            hv.x = (u32)__bfloat16_as_ushort(h0) | ((u32)__bfloat16_as_ushort(h1) << 16);
            hv.y = (u32)__bfloat16_as_ushort(h2) | ((u32)__bfloat16_as_ushort(h3) << 16);
            lv.x = (u32)__bfloat16_as_ushort(l0) | ((u32)__bfloat16_as_ushort(l1) << 16);
            lv.y = (u32)__bfloat16_as_ushort(l2) | ((u32)__bfloat16_as_ushort(l3) << 16);
            size_t e = (((size_t)img * HH + h) * WW + w) * CI + pass * 64 + cc * 4;
            *(uint2*)(g_act_hi + e) = hv;
            *(uint2*)(g_act_lo + e) = lv;
        }
    }
}

// ---------------------------------------------------------------------------
// conv_kernel: mma.sync bf16 implicit-GEMM conv3x3 + fused L2 normalize.
// CTA = (img, h). M=128(w) x N=128(cout). 18 stages of K=64 (tap x cin-half).
// Stage buffer 64KB: A_hi, A_lo [128w][64c], B_hi, B_lo [128co][64c],
// rows 128B, chunk XOR swizzle; cp.async double buffer.
// Warp layout 4(M) x 2(N); warp tile M=32 N=64; split terms:
//   acc += Ahi*Bhi + Alo*Bhi + Ahi*Blo.
// ---------------------------------------------------------------------------
#define CONV_SMEM (2 * 65536)

__global__ __launch_bounds__(256, 1)
void conv_kernel() {
    extern __shared__ char smem[];
    const u32 sb = smem_u32(smem);
    const int tid  = threadIdx.x;
    const int wid  = tid >> 5;
    const int lane = tid & 31;
    const int img  = blockIdx.x;
    const int h    = blockIdx.y;
    const int wm = wid & 3;          // M warp 0..3
    const int wn = wid >> 2;         // N warp 0..1
    const int qg = lane >> 2;        // quad group 0..7
    const int qt = lane & 3;         // quad thread 0..3

    // ldmatrix lane geometry (kk-independent parts)
    const int a_r0 = (lane & 7) + ((lane >> 3) & 1) * 8;  // A: row offset
    const int a_cs = (lane >> 4) & 1;                     // A: chunk select
    const int b_r0 = (lane & 7) + ((lane >> 4) & 1) * 8;  // B: row offset
    const int b_cs = (lane >> 3) & 1;                     // B: chunk select

    float acc[2][8][4];
#pragma unroll
    for (int i = 0; i < 2; i++)
#pragma unroll
        for (int j = 0; j < 8; j++)
#pragma unroll
            for (int c = 0; c < 4; c++) acc[i][j][c] = 0.f;

    auto issue_stage = [&](int s) {
        const int tap = s >> 1, half = s & 1;
        const int dy = tap / 3, dx = tap % 3;
        const int hsrc = h + dy - 1;
        const bool hok = (unsigned)hsrc < (unsigned)HH;
        const u32 buf = sb + (u32)(s & 1) * 65536u;
        for (int c = tid; c < 4096; c += 256) {
            const int region = c >> 10;          // 0:Ahi 1:Alo 2:Bhi 3:Blo
            const int q   = c & 1023;
            const int row = q >> 3;
            const int ch  = q & 7;
            const u32 dst = buf + (u32)region * 16384u + (u32)row * 128u
                          + (u32)((ch ^ (row & 7)) << 4);
            if (region < 2) {
                const int wsrc = row + dx - 1;
                const bool ok = hok && (unsigned)wsrc < (unsigned)WW;
                const __nv_bfloat16* base = region ? g_act_lo : g_act_hi;
                const __nv_bfloat16* src = base +
                    ((((size_t)img * HH + (ok ? hsrc : 0)) * WW
                      + (ok ? wsrc : 0)) * CI + half * 64 + ch * 8);
                CP_ASYNC16(dst, src, ok ? 16u : 0u);
            } else {
                const int tile = (tap * 2 + half) * 2 + (region - 2);
                const __nv_bfloat16* src = g_wb + (size_t)tile * 8192 + q * 8;
                CP_ASYNC16(dst, src, 16u);
            }
        }
        CP_COMMIT();
    };

    issue_stage(0);
    for (int s = 0; s < 18; s++) {
        if (s + 1 < 18) { issue_stage(s + 1); CP_WAIT1(); }
        else            { CP_WAIT0(); }
        __syncthreads();
        const u32 buf = sb + (u32)(s & 1) * 65536u;
        const u32 ah_b = buf, al_b = buf + 16384u;
        const u32 bh_b = buf + 32768u, bl_b = buf + 49152u;
#pragma unroll
        for (int kk = 0; kk < 4; kk++) {
            u32 Ah[2][4], Al[2][4], Bh[4][4], Bl[4][4];
#pragma unroll
            for (int i = 0; i < 2; i++) {
                const int row = wm * 32 + i * 16 + a_r0;
                const int ch  = kk * 2 + a_cs;
                const u32 off = (u32)row * 128u + (u32)((ch ^ (row & 7)) << 4);
                LDM4(Ah[i], ah_b + off);
                LDM4(Al[i], al_b + off);
            }
#pragma unroll
            for (int jj = 0; jj < 4; jj++) {
                const int row = wn * 64 + jj * 16 + b_r0;
                const int ch  = kk * 2 + b_cs;
                const u32 off = (u32)row * 128u + (u32)((ch ^ (row & 7)) << 4);
                LDM4(Bh[jj], bh_b + off);
                LDM4(Bl[jj], bl_b + off);
            }
#pragma unroll
            for (int i = 0; i < 2; i++)
#pragma unroll
                for (int j = 0; j < 8; j++) {
                    const u32 bh0 = Bh[j >> 1][(j & 1) * 2];
                    const u32 bh1 = Bh[j >> 1][(j & 1) * 2 + 1];
                    const u32 bl0 = Bl[j >> 1][(j & 1) * 2];
                    const u32 bl1 = Bl[j >> 1][(j & 1) * 2 + 1];
                    MMA16816(acc[i][j], Ah[i], bh0, bh1);
                    MMA16816(acc[i][j], Al[i], bh0, bh1);
                    MMA16816(acc[i][j], Ah[i], bl0, bl1);
                }
        }
        __syncthreads();
    }

    // ---- fused channel L2 norm epilogue ----
    // c-frag mapping: c0:(row qg, col 2qt) c1:(qg, 2qt+1) c2:(qg+8, 2qt) c3:(qg+8,+1)
    float* part = (float*)smem;   // [2 wn][128 w]
#pragma unroll
    for (int i = 0; i < 2; i++)
#pragma unroll
        for (int rh = 0; rh < 2; rh++) {
            float ssum = 0.f;
#pragma unroll
            for (int j = 0; j < 8; j++) {
                float c0 = acc[i][j][rh * 2], c1 = acc[i][j][rh * 2 + 1];
                ssum = fmaf(c0, c0, fmaf(c1, c1, ssum));
            }
            ssum += __shfl_xor_sync(0xFFFFFFFFu, ssum, 1);
            ssum += __shfl_xor_sync(0xFFFFFFFFu, ssum, 2);
            if (qt == 0)
                part[wn * 128 + wm * 32 + i * 16 + rh * 8 + qg] = ssum;
        }
    __syncthreads();
#pragma unroll
    for (int i = 0; i < 2; i++)
#pragma unroll
        for (int rh = 0; rh < 2; rh++) {
            const int r = wm * 32 + i * 16 + rh * 8 + qg;
            const float inv = rsqrtf(part[r] + part[128 + r]);
            float* dst = &g_nf[(((size_t)img * HH + h) * WW + r) * CO + wn * 64];
#pragma unroll
            for (int j = 0; j < 8; j++) {
                float2 o = make_float2(acc[i][j][rh * 2] * inv,
                                       acc[i][j][rh * 2 + 1] * inv);
                *(float2*)(dst + j * 8 + qt * 2) = o;
            }
        }
}

// ---------------------------------------------------------------------------
// corr_kernel (proven R1 scalar): out[b, pair*81+py*9+px, h, w] =
//   sum_c nf1[b,h,w,c] * nf2[b, h+2py-8, w+2px-8, c]
// ---------------------------------------------------------------------------
#define CK 8

__global__ __launch_bounds__(144)
void corr_kernel(float* __restrict__ out) {
    const int h    = blockIdx.x;
    const int pb   = blockIdx.y;
    const int pair = pb >> 2;
    const int b    = pb & 3;
    const int img1 = pair * 4 + b;
    const int img2 = img1 + 4;

    const int tid = threadIdx.x;
    const int py  = tid / 16;
    const int wg  = tid - py * 16;
    const int w0  = wg * 8;

    __shared__ float f2s[PATCH][CK][148];
    __shared__ float f1s[CK][132];

    float acc[8][PATCH];
#pragma unroll
    for (int i = 0; i < 8; i++)
#pragma unroll
        for (int j = 0; j < PATCH; j++) acc[i][j] = 0.f;

    for (int cch = 0; cch < CO / CK; cch++) {
        const int c0 = cch * CK;
        __syncthreads();
        for (int i = tid; i < WW * CK / 4; i += 144) {
            int w  = i >> 1;
            int c4 = (i & 1) * 4;
            float4 v = *(const float4*)
                (&g_nf[(((size_t)img1 * HH + h) * WW + w) * CO + c0 + c4]);
            f1s[c4 + 0][w] = v.x; f1s[c4 + 1][w] = v.y;
            f1s[c4 + 2][w] = v.z; f1s[c4 + 3][w] = v.w;
        }
        for (int i = tid; i < PATCH * 144 * CK / 4; i += 144) {
            int py2 = i / 288;
            int r   = i - py2 * 288;
            int col = r >> 1;
            int c4  = (r & 1) * 4;
            int row = h + py2 * 2 - PADC;
            int w2  = col - PADC;
            float4 v = make_float4(0.f, 0.f, 0.f, 0.f);
            if ((unsigned)row < (unsigned)HH && (unsigned)w2 < (unsigned)WW)
                v = *(const float4*)
                    (&g_nf[(((size_t)img2 * HH + row) * WW + w2) * CO + c0 + c4]);
            f2s[py2][c4 + 0][col] = v.x; f2s[py2][c4 + 1][col] = v.y;
            f2s[py2][c4 + 2][col] = v.z; f2s[py2][c4 + 3][col] = v.w;
        }
        __syncthreads();

#pragma unroll
        for (int c = 0; c < CK; c++) {
            float f1v[8];
            {
                const float* p = &f1s[c][w0];
                float4 a0 = *(const float4*)p;
                float4 a1 = *(const float4*)(p + 4);
                f1v[0] = a0.x; f1v[1] = a0.y; f1v[2] = a0.z; f1v[3] = a0.w;
                f1v[4] = a1.x; f1v[5] = a1.y; f1v[6] = a1.z; f1v[7] = a1.w;
            }
            float f2v[24];
            {
                const float* p = &f2s[py][c][w0];
#pragma unroll
                for (int q = 0; q < 6; q++) {
                    float4 v = *(const float4*)(p + q * 4);
                    f2v[q * 4 + 0] = v.x; f2v[q * 4 + 1] = v.y;
                    f2v[q * 4 + 2] = v.z; f2v[q * 4 + 3] = v.w;
                }
            }
#pragma unroll
            for (int wi = 0; wi < 8; wi++)
#pragma unroll
                for (int px = 0; px < PATCH; px++)
                    acc[wi][px] = fmaf(f1v[wi], f2v[wi + 2 * px], acc[wi][px]);
        }
    }

#pragma unroll
    for (int px = 0; px < PATCH; px++) {
        int ch = pair * (PATCH * PATCH) + py * PATCH + px;
        float* dst = &out[(((size_t)b * (3 * PATCH * PATCH) + ch) * HH + h) * WW + w0];
        *(float4*)dst       = make_float4(acc[0][px], acc[1][px], acc[2][px], acc[3][px]);
        *(float4*)(dst + 4) = make_float4(acc[4][px], acc[5][px], acc[6][px], acc[7][px]);
    }
}

// ---------------------------------------------------------------------------
extern "C" void kernel_launch(void* const* d_in, const int* in_sizes, int n_in,
                              void* d_out, int out_size) {
    const float* x     = (const float*)d_in[0];
    const float* gamma = (const float*)d_in[1];
    const float* beta  = (const float*)d_in[2];
    const float* mean  = (const float*)d_in[3];
    const float* var   = (const float*)d_in[4];
    const float* convw = (const float*)d_in[5];
    float* out = (float*)d_out;

    cudaFuncSetAttribute(conv_kernel,
                         cudaFuncAttributeMaxDynamicSharedMemorySize, CONV_SMEM);

    prep_bn_kernel<<<1, 128>>>(gamma, beta, mean, var);
    prep_w_kernel<<<36, 256>>>(convw);
    act_split_kernel<<<dim3(NIMG, HH), 256>>>(x);
    conv_kernel<<<dim3(NIMG, HH), 256, CONV_SMEM>>>();
    corr_kernel<<<dim3(HH, 3 * BB), 144>>>(out);
}

// round 7
// speedup vs baseline: 2.8955x; 1.1222x over previous
#include <cuda_runtime.h>
#include <cuda_bf16.h>
#include <cstdint>

// ---------------------------------------------------------------------------
// CorrelationModule on sm_100 (base target -- NO tcgen05, NO f32x2):
//   BN+ReLU -> conv3x3 as mma.sync bf16 split-precision implicit GEMM
//   -> fused channel L2 norm (bf16 hi/lo output)
//   -> 9x9 dilated correlation ALSO on mma.sync (parity-split Toeplitz GEMM).
// ---------------------------------------------------------------------------

#define BB    4
#define GG    4
#define CI    128
#define CO    128
#define HH    64
#define WW    128
#define NIMG  16
#define PATCH 9
#define PADC  8

typedef unsigned int u32;

// ------------------------------ device scratch -----------------------------
__device__ __align__(128) __nv_bfloat16  g_nfh[NIMG * HH * WW * CO];     // 32 MB
__device__ __align__(128) __nv_bfloat16  g_nfl[NIMG * HH * WW * CO];     // 32 MB
__device__ __align__(128) __nv_bfloat16  g_act_hi[NIMG * HH * WW * CI];  // 32 MB
__device__ __align__(128) __nv_bfloat16  g_act_lo[NIMG * HH * WW * CI];  // 32 MB
// weight tiles: tile = (tap*2 + half)*2 + split, each [cout=128][c=64] bf16
__device__ __align__(128) __nv_bfloat16  g_wb[36 * 128 * 64];
__device__ float g_bn_a[CI];
__device__ float g_bn_b[CI];

// ------------------------------ helpers ------------------------------------
__device__ __forceinline__ u32 smem_u32(const void* p) {
    u32 a;
    asm("{ .reg .u64 t; cvta.to.shared.u64 t, %1; cvt.u32.u64 %0, t; }"
        : "=r"(a) : "l"(p));
    return a;
}

#define LDM4(r, addr) \
    asm volatile("ldmatrix.sync.aligned.m8n8.x4.shared.b16 {%0,%1,%2,%3}, [%4];" \
        : "=r"((r)[0]), "=r"((r)[1]), "=r"((r)[2]), "=r"((r)[3]) : "r"(addr))
#define LDM2(r, addr) \
    asm volatile("ldmatrix.sync.aligned.m8n8.x2.shared.b16 {%0,%1}, [%2];" \
        : "=r"((r)[0]), "=r"((r)[1]) : "r"(addr))

#define MMA16816(d, a, b0_, b1_) \
    asm volatile("mma.sync.aligned.m16n8k16.row.col.f32.bf16.bf16.f32 " \
        "{%0,%1,%2,%3}, {%4,%5,%6,%7}, {%8,%9}, {%0,%1,%2,%3};" \
        : "+f"((d)[0]), "+f"((d)[1]), "+f"((d)[2]), "+f"((d)[3]) \
        : "r"((a)[0]), "r"((a)[1]), "r"((a)[2]), "r"((a)[3]), "r"(b0_), "r"(b1_))

#define CP_ASYNC16(dst, src, sz) \
    asm volatile("cp.async.cg.shared.global [%0], [%1], 16, %2;" \
                 :: "r"(dst), "l"(src), "r"(sz) : "memory")
#define CP_COMMIT() asm volatile("cp.async.commit_group;" ::: "memory")
#define CP_WAIT1()  asm volatile("cp.async.wait_group 1;" ::: "memory")
#define CP_WAIT0()  asm volatile("cp.async.wait_group 0;" ::: "memory")

__device__ __forceinline__ u32 pack_bf2(float a, float b) {
    __nv_bfloat16 x = __float2bfloat16(a), y = __float2bfloat16(b);
    return (u32)__bfloat16_as_ushort(x) | ((u32)__bfloat16_as_ushort(y) << 16);
}

// ---------------------------------------------------------------------------
// prep_bn
// ---------------------------------------------------------------------------
__global__ void prep_bn_kernel(const float* __restrict__ gamma,
                               const float* __restrict__ beta,
                               const float* __restrict__ mean,
                               const float* __restrict__ var) {
    int c = threadIdx.x;
    if (c < CI) {
        float a = gamma[c] * rsqrtf(var[c] + 1e-5f);
        g_bn_a[c] = a;
        g_bn_b[c] = beta[c] - mean[c] * a;
    }
}

// ---------------------------------------------------------------------------
// prep_w: split weights into bf16 hi/lo tiles [cout][64c] per (tap, half).
// ---------------------------------------------------------------------------
__global__ void prep_w_kernel(const float* __restrict__ convw) {
    int im   = blockIdx.x;              // 0..35
    int sp   = im & 1;
    int half = (im >> 1) & 1;
    int tap  = im >> 2;
    int dy = tap / 3, dx = tap % 3;
    __nv_bfloat16* base = g_wb + (size_t)im * 8192;
    for (int t = threadIdx.x; t < 128 * 64; t += 256) {
        int cout = t >> 6;
        int cl   = t & 63;
        int cin  = half * 64 + cl;
        float wv = convw[(cout * CI + cin) * 9 + dy * 3 + dx];
        __nv_bfloat16 hi = __float2bfloat16(wv);
        base[t] = (sp == 0) ? hi : __float2bfloat16(wv - __bfloat162float(hi));
    }
}

// ---------------------------------------------------------------------------
// act_split: BN+ReLU, fp32 -> (hi,lo) bf16, NCHW -> NHWC transpose.
// ---------------------------------------------------------------------------
__global__ __launch_bounds__(256)
void act_split_kernel(const float* __restrict__ x) {
    const int img = blockIdx.x, h = blockIdx.y;
    const int g = img >> 2, b = img & 3;
    __shared__ float s[64 * 133];
    const int tid = threadIdx.x;
    const int c2 = tid >> 7;
    const int wl = tid & 127;

    for (int pass = 0; pass < 2; pass++) {
        __syncthreads();
        for (int co = 0; co < 64; co += 2) {
            int cl  = co + c2;
            int cin = pass * 64 + cl;
            float xv = x[(((size_t)b * 512 + g * 128 + cin) * HH + h) * WW + wl];
            s[cl * 133 + wl] = fmaxf(fmaf(xv, g_bn_a[cin], g_bn_b[cin]), 0.f);
        }
        __syncthreads();
        for (int t = tid; t < 2048; t += 256) {
            int w  = t >> 4;
            int cc = t & 15;
            float v0 = s[(cc * 4 + 0) * 133 + w];
            float v1 = s[(cc * 4 + 1) * 133 + w];
            float v2 = s[(cc * 4 + 2) * 133 + w];
            float v3 = s[(cc * 4 + 3) * 133 + w];
            __nv_bfloat16 h0 = __float2bfloat16(v0), h1 = __float2bfloat16(v1);
            __nv_bfloat16 h2 = __float2bfloat16(v2), h3 = __float2bfloat16(v3);
            uint2 hv, lv;
            hv.x = (u32)__bfloat16_as_ushort(h0) | ((u32)__bfloat16_as_ushort(h1) << 16);
            hv.y = (u32)__bfloat16_as_ushort(h2) | ((u32)__bfloat16_as_ushort(h3) << 16);
            lv.x = pack_bf2(v0 - __bfloat162float(h0), v1 - __bfloat162float(h1));
            lv.y = pack_bf2(v2 - __bfloat162float(h2), v3 - __bfloat162float(h3));
            size_t e = (((size_t)img * HH + h) * WW + w) * CI + pass * 64 + cc * 4;
            *(uint2*)(g_act_hi + e) = hv;
            *(uint2*)(g_act_lo + e) = lv;
        }
    }
}

// ---------------------------------------------------------------------------
// conv_kernel (proven R5 body): mma.sync bf16 implicit-GEMM conv3x3 +
// fused L2 norm; epilogue emits normalized features as bf16 hi/lo.
// ---------------------------------------------------------------------------
#define CONV_SMEM (2 * 65536)

__global__ __launch_bounds__(256, 1)
void conv_kernel() {
    extern __shared__ char smem[];
    const u32 sb = smem_u32(smem);
    const int tid  = threadIdx.x;
    const int wid  = tid >> 5;
    const int lane = tid & 31;
    const int img  = blockIdx.x;
    const int h    = blockIdx.y;
    const int wm = wid & 3;
    const int wn = wid >> 2;
    const int qg = lane >> 2;
    const int qt = lane & 3;

    const int a_r0 = (lane & 7) + ((lane >> 3) & 1) * 8;
    const int a_cs = (lane >> 4) & 1;
    const int b_r0 = (lane & 7) + ((lane >> 4) & 1) * 8;
    const int b_cs = (lane >> 3) & 1;

    float acc[2][8][4];
#pragma unroll
    for (int i = 0; i < 2; i++)
#pragma unroll
        for (int j = 0; j < 8; j++)
#pragma unroll
            for (int c = 0; c < 4; c++) acc[i][j][c] = 0.f;

    auto issue_stage = [&](int s) {
        const int tap = s >> 1, half = s & 1;
        const int dy = tap / 3, dx = tap % 3;
        const int hsrc = h + dy - 1;
        const bool hok = (unsigned)hsrc < (unsigned)HH;
        const u32 buf = sb + (u32)(s & 1) * 65536u;
        for (int c = tid; c < 4096; c += 256) {
            const int region = c >> 10;
            const int q   = c & 1023;
            const int row = q >> 3;
            const int ch  = q & 7;
            const u32 dst = buf + (u32)region * 16384u + (u32)row * 128u
                          + (u32)((ch ^ (row & 7)) << 4);
            if (region < 2) {
                const int wsrc = row + dx - 1;
                const bool ok = hok && (unsigned)wsrc < (unsigned)WW;
                const __nv_bfloat16* base = region ? g_act_lo : g_act_hi;
                const __nv_bfloat16* src = base +
                    ((((size_t)img * HH + (ok ? hsrc : 0)) * WW
                      + (ok ? wsrc : 0)) * CI + half * 64 + ch * 8);
                CP_ASYNC16(dst, src, ok ? 16u : 0u);
            } else {
                const int tile = (tap * 2 + half) * 2 + (region - 2);
                const __nv_bfloat16* src = g_wb + (size_t)tile * 8192 + q * 8;
                CP_ASYNC16(dst, src, 16u);
            }
        }
        CP_COMMIT();
    };

    issue_stage(0);
    for (int s = 0; s < 18; s++) {
        if (s + 1 < 18) { issue_stage(s + 1); CP_WAIT1(); }
        else            { CP_WAIT0(); }
        __syncthreads();
        const u32 buf = sb + (u32)(s & 1) * 65536u;
        const u32 ah_b = buf, al_b = buf + 16384u;
        const u32 bh_b = buf + 32768u, bl_b = buf + 49152u;
#pragma unroll
        for (int kk = 0; kk < 4; kk++) {
            u32 Ah[2][4], Al[2][4], Bh[4][4], Bl[4][4];
#pragma unroll
            for (int i = 0; i < 2; i++) {
                const int row = wm * 32 + i * 16 + a_r0;
                const int ch  = kk * 2 + a_cs;
                const u32 off = (u32)row * 128u + (u32)((ch ^ (row & 7)) << 4);
                LDM4(Ah[i], ah_b + off);
                LDM4(Al[i], al_b + off);
            }
#pragma unroll
            for (int jj = 0; jj < 4; jj++) {
                const int row = wn * 64 + jj * 16 + b_r0;
                const int ch  = kk * 2 + b_cs;
                const u32 off = (u32)row * 128u + (u32)((ch ^ (row & 7)) << 4);
                LDM4(Bh[jj], bh_b + off);
                LDM4(Bl[jj], bl_b + off);
            }
#pragma unroll
            for (int i = 0; i < 2; i++)
#pragma unroll
                for (int j = 0; j < 8; j++) {
                    const u32 bh0 = Bh[j >> 1][(j & 1) * 2];
                    const u32 bh1 = Bh[j >> 1][(j & 1) * 2 + 1];
                    const u32 bl0 = Bl[j >> 1][(j & 1) * 2];
                    const u32 bl1 = Bl[j >> 1][(j & 1) * 2 + 1];
                    MMA16816(acc[i][j], Ah[i], bh0, bh1);
                    MMA16816(acc[i][j], Al[i], bh0, bh1);
                    MMA16816(acc[i][j], Ah[i], bl0, bl1);
                }
        }
        __syncthreads();
    }

    // ---- fused channel L2 norm epilogue (bf16 hi/lo output) ----
    float* part = (float*)smem;   // [2 wn][128 w]
#pragma unroll
    for (int i = 0; i < 2; i++)
#pragma unroll
        for (int rh = 0; rh < 2; rh++) {
            float ssum = 0.f;
#pragma unroll
            for (int j = 0; j < 8; j++) {
                float c0 = acc[i][j][rh * 2], c1 = acc[i][j][rh * 2 + 1];
                ssum = fmaf(c0, c0, fmaf(c1, c1, ssum));
            }
            ssum += __shfl_xor_sync(0xFFFFFFFFu, ssum, 1);
            ssum += __shfl_xor_sync(0xFFFFFFFFu, ssum, 2);
            if (qt == 0)
                part[wn * 128 + wm * 32 + i * 16 + rh * 8 + qg] = ssum;
        }
    __syncthreads();
#pragma unroll
    for (int i = 0; i < 2; i++)
#pragma unroll
        for (int rh = 0; rh < 2; rh++) {
            const int r = wm * 32 + i * 16 + rh * 8 + qg;
            const float inv = rsqrtf(part[r] + part[128 + r]);
            const size_t base = (((size_t)img * HH + h) * WW + r) * CO + wn * 64;
#pragma unroll
            for (int j = 0; j < 8; j++) {
                float v0 = acc[i][j][rh * 2] * inv;
                float v1 = acc[i][j][rh * 2 + 1] * inv;
                __nv_bfloat16 h0 = __float2bfloat16(v0);
                __nv_bfloat16 h1 = __float2bfloat16(v1);
                u32 hv = (u32)__bfloat16_as_ushort(h0)
                       | ((u32)__bfloat16_as_ushort(h1) << 16);
                u32 lv = pack_bf2(v0 - __bfloat162float(h0),
                                  v1 - __bfloat162float(h1));
                *(u32*)(g_nfh + base + j * 8 + qt * 2) = hv;
                *(u32*)(g_nfl + base + j * 8 + qt * 2) = lv;
            }
        }
}

// ---------------------------------------------------------------------------
// corr_kernel (tensor): parity-split Toeplitz GEMM.
// Block = (h, pair*4+b), 256 thr = 8 warps; warp = (parity, w-tile of 16).
// f1 row resident in smem [chalf][split][par][64 rows][128B] (64 KB).
// Loop it = py*2 + chalf (18 iters): stream f2 [split][par][72 rows][128B]
// (36 KB, double buffered). Per warp per kstep: A hi/lo LDM4, B 3 tiles
// (LDM4 + LDM2) hi/lo, 9 HMMA (3 tiles x 3 split terms).
// px = colpad_local - wrow_local; per-py extraction to smem then coalesced.
// ---------------------------------------------------------------------------
#define CORR_F2OFF  65536
#define CORR_F2BUF  36864
#define CORR_OUTOFF (65536 + 2 * 36864)
#define CORR_SMEM   (65536 + 2 * 36864 + 4800)

__global__ __launch_bounds__(256, 1)
void corr_kernel(float* __restrict__ out) {
    extern __shared__ char smem[];
    const u32 sb = smem_u32(smem);
    const int tid  = threadIdx.x;
    const int wid  = tid >> 5;
    const int lane = tid & 31;
    const int h    = blockIdx.x;          // 0..63
    const int pb   = blockIdx.y;          // 0..11
    const int pair = pb >> 2, b = pb & 3;
    const int img1 = pair * 4 + b;
    const int img2 = img1 + 4;
    const int pp   = wid & 1;             // w parity
    const int idx  = wid >> 1;            // w-tile 0..3
    const int qg = lane >> 2, qt = lane & 3;
    const int a_r0 = (lane & 7) + ((lane >> 3) & 1) * 8;
    const int a_cs = (lane >> 4) & 1;
    const int b_r0 = (lane & 7) + ((lane >> 4) & 1) * 8;
    const int b_cs = (lane >> 3) & 1;

    // ---- f1 prologue: [chalf][split][par][64 rows][128B], conv swizzle
    for (int t = tid; t < 4096; t += 256) {
        const int ch  = t & 7;
        const int row = (t >> 3) & 63;
        const int par = (t >> 9) & 1;
        const int sp  = (t >> 10) & 1;
        const int chf = (t >> 11) & 1;
        const int w   = par + 2 * row;
        const __nv_bfloat16* src = (sp ? g_nfl : g_nfh) +
            ((((size_t)img1 * HH + h) * WW + w) * CO + chf * 64 + ch * 8);
        const u32 dst = sb + (u32)((((chf * 2 + sp) * 2 + par) * 64 + row) * 128)
                      + (u32)((ch ^ (row & 7)) << 4);
        CP_ASYNC16(dst, src, 16u);
    }

    auto issue_f2 = [&](int it) {          // it = py*2 + chalf
        const int py  = it >> 1;
        const int chf = it & 1;
        const int h2  = h + 2 * py - 8;
        const bool hok = (unsigned)h2 < (unsigned)HH;
        const u32 buf = sb + CORR_F2OFF + (u32)(it & 1) * CORR_F2BUF;
        for (int t = tid; t < 2304; t += 256) {
            const int ch   = t & 7;
            const int rr   = t >> 3;       // 0..287
            const int row  = rr % 72;      // colpad
            const int rest = rr / 72;      // sp*2 + par
            const int par = rest & 1, sp = rest >> 1;
            const int w2 = par + 2 * (row - 4);
            const bool ok = hok && (unsigned)w2 < (unsigned)WW;
            const __nv_bfloat16* src = (sp ? g_nfl : g_nfh) +
                ((((size_t)img2 * HH + (ok ? h2 : 0)) * WW + (ok ? w2 : 0)) * CO
                 + chf * 64 + ch * 8);
            const u32 dst = buf + (u32)(((sp * 2 + par) * 72 + row) * 128)
                          + (u32)((ch ^ (row & 7)) << 4);
            CP_ASYNC16(dst, src, ok ? 16u : 0u);
        }
        CP_COMMIT();
    };

    issue_f2(0);                           // group0 = f1 + f2(it 0)
    float acc[3][4];
    float* ost = (float*)(smem + CORR_OUTOFF);

    for (int it = 0; it < 18; it++) {
        if (it + 1 < 18) { issue_f2(it + 1); CP_WAIT1(); }
        else             { CP_WAIT0(); }
        __syncthreads();
        const int chf = it & 1;
        if (chf == 0) {
#pragma unroll
            for (int t2 = 0; t2 < 3; t2++)
#pragma unroll
                for (int c = 0; c < 4; c++) acc[t2][c] = 0.f;
        }
        const u32 f2b = sb + CORR_F2OFF + (u32)(it & 1) * CORR_F2BUF;
#pragma unroll
        for (int kk = 0; kk < 4; kk++) {
            u32 Ah[4], Al[4], Bh[6], Bl[6];
            {   // A: f1 region (chf, sp, pp), rows idx*16 + a_r0
                const int row = idx * 16 + a_r0;
                const int ch  = kk * 2 + a_cs;
                const u32 swz = (u32)((ch ^ (row & 7)) << 4);
                const u32 oh = sb + (u32)((((chf * 2 + 0) * 2 + pp) * 64 + row) * 128) + swz;
                const u32 ol = sb + (u32)((((chf * 2 + 1) * 2 + pp) * 64 + row) * 128) + swz;
                LDM4(Ah, oh);
                LDM4(Al, ol);
            }
            {   // B tiles 0,1 (cols 16idx..+15): LDM4
                const int row = idx * 16 + b_r0;
                const int ch  = kk * 2 + b_cs;
                const u32 swz = (u32)((ch ^ (row & 7)) << 4);
                const u32 oh = f2b + (u32)(((0 * 2 + pp) * 72 + row) * 128) + swz;
                const u32 ol = f2b + (u32)(((1 * 2 + pp) * 72 + row) * 128) + swz;
                LDM4(Bh, oh);
                LDM4(Bl, ol);
            }
            {   // B tile 2 (cols 16idx+16..+23): LDM2 (lanes 0-15 addresses)
                const int row = idx * 16 + 16 + (lane & 7);
                const int ch  = kk * 2 + ((lane >> 3) & 1);
                const u32 swz = (u32)((ch ^ (row & 7)) << 4);
                const u32 oh = f2b + (u32)(((0 * 2 + pp) * 72 + row) * 128) + swz;
                const u32 ol = f2b + (u32)(((1 * 2 + pp) * 72 + row) * 128) + swz;
                LDM2(Bh + 4, oh);
                LDM2(Bl + 4, ol);
            }
#pragma unroll
            for (int t2 = 0; t2 < 3; t2++) {
                const u32 bh0 = Bh[t2 * 2], bh1 = Bh[t2 * 2 + 1];
                const u32 bl0 = Bl[t2 * 2], bl1 = Bl[t2 * 2 + 1];
                MMA16816(acc[t2], Ah, bh0, bh1);
                MMA16816(acc[t2], Al, bh0, bh1);
                MMA16816(acc[t2], Ah, bl0, bl1);
            }
        }
        if (chf == 1) {
            const int py = it >> 1;
            // extraction: px = (8t + 2qt + (reg&1)) - (qg + 8*(reg>>1))
#pragma unroll
            for (int t2 = 0; t2 < 3; t2++)
#pragma unroll
                for (int reg = 0; reg < 4; reg++) {
                    const int r  = qg + 8 * (reg >> 1);
                    const int j  = 8 * t2 + 2 * qt + (reg & 1);
                    const int px = j - r;
                    if ((unsigned)px <= 8u) {
                        const int w = pp + 2 * (16 * idx + r);
                        ost[px * 132 + w] = acc[t2][reg];
                    }
                }
            __syncthreads();
            for (int t2 = tid; t2 < 1152; t2 += 256) {
                const int px = t2 >> 7;
                const int w  = t2 & 127;
                out[(((size_t)b * 243 + pair * 81 + py * 9 + px) * HH + h) * WW + w]
                    = ost[px * 132 + w];
            }
        }
        __syncthreads();
    }
}

// ---------------------------------------------------------------------------
extern "C" void kernel_launch(void* const* d_in, const int* in_sizes, int n_in,
                              void* d_out, int out_size) {
    const float* x     = (const float*)d_in[0];
    const float* gamma = (const float*)d_in[1];
    const float* beta  = (const float*)d_in[2];
    const float* mean  = (const float*)d_in[3];
    const float* var   = (const float*)d_in[4];
    const float* convw = (const float*)d_in[5];
    float* out = (float*)d_out;

    cudaFuncSetAttribute(conv_kernel,
                         cudaFuncAttributeMaxDynamicSharedMemorySize, CONV_SMEM);
    cudaFuncSetAttribute(corr_kernel,
                         cudaFuncAttributeMaxDynamicSharedMemorySize, CORR_SMEM);

    prep_bn_kernel<<<1, 128>>>(gamma, beta, mean, var);
    prep_w_kernel<<<36, 256>>>(convw);
    act_split_kernel<<<dim3(NIMG, HH), 256>>>(x);
    conv_kernel<<<dim3(NIMG, HH), 256, CONV_SMEM>>>();
    corr_kernel<<<dim3(HH, 3 * BB), 256, CORR_SMEM>>>(out);
}